// round 3
// baseline (speedup 1.0000x reference)
#include <cuda_runtime.h>
#include <cuda_bf16.h>
#include <math.h>

#define TT 2048
#define DD 1024
#define NH 8
#define HD 128
#define GATE_IN 12

static __device__ float g_qkv[(size_t)TT * 3 * DD];   // [t][3*D]
static __device__ float g_q[(size_t)NH * TT * HD];    // [h][t][hd]
static __device__ float g_k[(size_t)NH * TT * HD];
static __device__ float g_v[(size_t)NH * TT * HD];
static __device__ float g_y[(size_t)TT * DD];         // [t][h*HD+hd]

#define ATTN_SCALE 0.12f
#define RMS_EPS 1e-6f
#define LOG2E 1.4426950408889634f

// ---------------------------------------------------------------------------
// GEMM: C[m][n] = sum_k A[m*K+k] * B[n*K+k]   (A row-major MxK, B row-major NxK)
// Tiles: BM=BN=128, BK=16, 256 threads, 8x8 microtile per thread.
// MODE 0: A = external (x), C = g_qkv (QKV projection)
// MODE 1: A = g_y,         C = external (out) (O projection)
// ---------------------------------------------------------------------------
template <int MODE>
__global__ void __launch_bounds__(256) gemm_abt_kernel(
    const float* __restrict__ Aext, const float* __restrict__ B,
    float* __restrict__ Cext, int M, int N, int K)
{
    const float* __restrict__ A = (MODE == 0) ? Aext : (const float*)g_y;
    float* __restrict__ C       = (MODE == 0) ? (float*)g_qkv : Cext;

    constexpr int BM = 128, BN = 128, BK = 16;
    __shared__ __align__(16) float As[BK][BM];
    __shared__ __align__(16) float Bs[BK][BN];

    const int tid = threadIdx.x;
    const int bm = blockIdx.y * BM;
    const int bn = blockIdx.x * BN;

    const int ty = tid >> 4;        // 0..15 -> row group
    const int tx = tid & 15;        // 0..15 -> col group
    const int tm = ty * 8;
    const int tn = tx * 8;

    // load mapping: 64 rows x 4 float4 cols per pass, 2 passes
    const int lrow = tid >> 2;            // 0..63
    const int lcol4 = (tid & 3) * 4;      // 0,4,8,12

    const float* Ab = A + (size_t)bm * K;
    const float* Bb = B + (size_t)bn * K;

    float acc[8][8];
#pragma unroll
    for (int i = 0; i < 8; i++)
#pragma unroll
        for (int j = 0; j < 8; j++) acc[i][j] = 0.f;

    for (int kt = 0; kt < K; kt += BK) {
        __syncthreads();
#pragma unroll
        for (int p = 0; p < 2; p++) {
            int m = lrow + p * 64;
            float4 av = *(const float4*)(Ab + (size_t)m * K + kt + lcol4);
            As[lcol4 + 0][m] = av.x;
            As[lcol4 + 1][m] = av.y;
            As[lcol4 + 2][m] = av.z;
            As[lcol4 + 3][m] = av.w;
            float4 bv = *(const float4*)(Bb + (size_t)m * K + kt + lcol4);
            Bs[lcol4 + 0][m] = bv.x;
            Bs[lcol4 + 1][m] = bv.y;
            Bs[lcol4 + 2][m] = bv.z;
            Bs[lcol4 + 3][m] = bv.w;
        }
        __syncthreads();

#pragma unroll
        for (int k = 0; k < BK; k++) {
            float4 a0 = *(const float4*)&As[k][tm];
            float4 a1 = *(const float4*)&As[k][tm + 4];
            float4 b0 = *(const float4*)&Bs[k][tn];
            float4 b1 = *(const float4*)&Bs[k][tn + 4];
            float a[8] = {a0.x, a0.y, a0.z, a0.w, a1.x, a1.y, a1.z, a1.w};
            float b[8] = {b0.x, b0.y, b0.z, b0.w, b1.x, b1.y, b1.z, b1.w};
#pragma unroll
            for (int i = 0; i < 8; i++)
#pragma unroll
                for (int j = 0; j < 8; j++) acc[i][j] += a[i] * b[j];
        }
    }

#pragma unroll
    for (int i = 0; i < 8; i++) {
        float* Crow = C + (size_t)(bm + tm + i) * N + bn + tn;
        float4 v0 = make_float4(acc[i][0], acc[i][1], acc[i][2], acc[i][3]);
        float4 v1 = make_float4(acc[i][4], acc[i][5], acc[i][6], acc[i][7]);
        *(float4*)(Crow) = v0;
        *(float4*)(Crow + 4) = v1;
    }
}

// ---------------------------------------------------------------------------
// Postprocess: per (t,h): rms_norm + rotary on q,k; v = l0*v + l1*ve.
// Writes per-head contiguous layouts g_q/g_k/g_v [h][t][hd].
// One block = one (t,h), 128 threads.
// ---------------------------------------------------------------------------
__global__ void postproc_kernel(const float* __restrict__ ve,
                                const float* __restrict__ lam,
                                const float* __restrict__ cosb,
                                const float* __restrict__ sinb)
{
    const int t = blockIdx.x >> 3;
    const int h = blockIdx.x & 7;
    const int hd = threadIdx.x;

    const float* row = g_qkv + (size_t)t * (3 * DD) + h * HD;
    float qv = row[hd];
    float kv = row[DD + hd];
    float vv = row[2 * DD + hd];

    float sq = qv * qv, sk = kv * kv;
#pragma unroll
    for (int o = 16; o; o >>= 1) {
        sq += __shfl_xor_sync(0xffffffffu, sq, o);
        sk += __shfl_xor_sync(0xffffffffu, sk, o);
    }
    __shared__ float red[2][4];
    int w = hd >> 5, lane = hd & 31;
    if (lane == 0) { red[0][w] = sq; red[1][w] = sk; }
    __syncthreads();
    sq = red[0][0] + red[0][1] + red[0][2] + red[0][3];
    sk = red[1][0] + red[1][1] + red[1][2] + red[1][3];
    float qr = rsqrtf(sq * (1.0f / HD) + RMS_EPS);
    float kr = rsqrtf(sk * (1.0f / HD) + RMS_EPS);

    __shared__ float qn[HD], kn[HD];
    qn[hd] = qv * qr;
    kn[hd] = kv * kr;
    __syncthreads();

    float qo, ko;
    if (hd < 64) {
        float c = cosb[t * 64 + hd];
        float s = sinb[t * 64 + hd];
        qo = qn[hd] * c + qn[hd + 64] * s;
        ko = kn[hd] * c + kn[hd + 64] * s;
    } else {
        int j = hd - 64;
        float c = cosb[t * 64 + j];
        float s = sinb[t * 64 + j];
        qo = -qn[j] * s + qn[hd] * c;
        ko = -kn[j] * s + kn[hd] * c;
    }
    const float l0 = __ldg(lam);
    const float l1 = __ldg(lam + 1);
    size_t oidx = ((size_t)h * TT + t) * HD + hd;
    g_q[oidx] = qo;
    g_k[oidx] = ko;
    g_v[oidx] = l0 * vv + l1 * ve[((size_t)t * NH + h) * HD + hd];
}

// ---------------------------------------------------------------------------
// Flash attention (fp32, online softmax). Grid: (T/64, H), 256 threads.
// 4 threads per q-row; thread quad q owns interleaved float4 groups 4g+q
// (conflict-free smem broadcast pattern). Gate fused into epilogue.
// ---------------------------------------------------------------------------
__global__ void __launch_bounds__(256) flash_kernel(
    const float* __restrict__ x, const float* __restrict__ gate_w)
{
    constexpr int BQ = 64, BK = 32;
    const int h = blockIdx.y;
    const int qb = blockIdx.x;
    const int tid = threadIdx.x;
    const int r = tid >> 2;          // 0..63 row in tile
    const int q4 = tid & 3;          // col quad
    const int qrow = qb * BQ + r;

    const float* Qh = g_q + (size_t)h * TT * HD;
    const float* Kh = g_k + (size_t)h * TT * HD;
    const float* Vh = g_v + (size_t)h * TT * HD;

    __shared__ float4 Ks4[BK][32];
    __shared__ float4 Vs4[BK][32];

    float4 qf[8], o4[8];
    const float4* Qr = (const float4*)(Qh + (size_t)qrow * HD);
#pragma unroll
    for (int g = 0; g < 8; g++) {
        qf[g] = Qr[4 * g + q4];
        o4[g] = make_float4(0.f, 0.f, 0.f, 0.f);
    }

    float m = -INFINITY, l = 0.f;
    const int nt = (qb + 1) * (BQ / BK);

    for (int kt = 0; kt < nt; kt++) {
        const int k0 = kt * BK;
        __syncthreads();
        const float4* K4 = (const float4*)(Kh + (size_t)k0 * HD);
        const float4* V4 = (const float4*)(Vh + (size_t)k0 * HD);
#pragma unroll
        for (int i = 0; i < 4; i++) {
            int idx = tid + i * 256;
            (&Ks4[0][0])[idx] = K4[idx];
            (&Vs4[0][0])[idx] = V4[idx];
        }
        __syncthreads();

        float p[BK];
        float mt = m;
#pragma unroll
        for (int kk = 0; kk < BK; kk++) {
            float acc = 0.f;
#pragma unroll
            for (int g = 0; g < 8; g++) {
                float4 kv = Ks4[kk][4 * g + q4];
                acc += qf[g].x * kv.x;
                acc += qf[g].y * kv.y;
                acc += qf[g].z * kv.z;
                acc += qf[g].w * kv.w;
            }
            acc += __shfl_xor_sync(0xffffffffu, acc, 1);
            acc += __shfl_xor_sync(0xffffffffu, acc, 2);
            acc *= ATTN_SCALE;
            p[kk] = (k0 + kk > qrow) ? -INFINITY : acc;
            mt = fmaxf(mt, p[kk]);
        }

        float corr = exp2f((m - mt) * LOG2E);
        float ps = 0.f;
#pragma unroll
        for (int kk = 0; kk < BK; kk++) {
            float e = exp2f((p[kk] - mt) * LOG2E);
            p[kk] = e;
            ps += e;
        }
        l = l * corr + ps;
        m = mt;
#pragma unroll
        for (int g = 0; g < 8; g++) {
            o4[g].x *= corr; o4[g].y *= corr; o4[g].z *= corr; o4[g].w *= corr;
        }
#pragma unroll
        for (int kk = 0; kk < BK; kk++) {
            float pk = p[kk];
#pragma unroll
            for (int g = 0; g < 8; g++) {
                float4 vv = Vs4[kk][4 * g + q4];
                o4[g].x += pk * vv.x;
                o4[g].y += pk * vv.y;
                o4[g].z += pk * vv.z;
                o4[g].w += pk * vv.w;
            }
        }
    }

    // gate = sigmoid(x[t,0:12] . gate_w[h,:])
    float gg = 0.f;
#pragma unroll
    for (int i = 0; i < GATE_IN; i++)
        gg += x[(size_t)qrow * DD + i] * gate_w[h * GATE_IN + i];
    gg = 1.f / (1.f + expf(-gg));

    float inv = gg / l;
    float4* Yr = (float4*)(g_y + (size_t)qrow * DD + h * HD);
#pragma unroll
    for (int g = 0; g < 8; g++) {
        float4 ov = o4[g];
        ov.x *= inv; ov.y *= inv; ov.z *= inv; ov.w *= inv;
        Yr[4 * g + q4] = ov;
    }
}

// ---------------------------------------------------------------------------
extern "C" void kernel_launch(void* const* d_in, const int* in_sizes, int n_in,
                              void* d_out, int out_size)
{
    const float* x      = (const float*)d_in[0];  // (1,2048,1024)
    const float* qkvo_w = (const float*)d_in[1];  // (4,1024,1024)
    const float* gate_w = (const float*)d_in[2];  // (8,12)
    const float* ve     = (const float*)d_in[3];  // (1,2048,8,128)
    const float* lam    = (const float*)d_in[4];  // (2,)
    const float* cosb   = (const float*)d_in[5];  // (2048,64)
    const float* sinb   = (const float*)d_in[6];  // (2048,64)
    float* out = (float*)d_out;                   // (1,2048,1024)

    // 1) QKV = x @ W_qkv^T   (2048 x 3072 x 1024) -> g_qkv
    {
        dim3 grid(3072 / 128, 2048 / 128);
        gemm_abt_kernel<0><<<grid, 256>>>(x, qkvo_w, nullptr, TT, 3 * DD, DD);
    }
    // 2) rms_norm + rotary + value mix
    postproc_kernel<<<TT * NH, 128>>>(ve, lam, cosb, sinb);
    // 3) causal flash attention + gate -> g_y
    {
        dim3 grid(TT / 64, NH);
        flash_kernel<<<grid, 256>>>(x, gate_w);
    }
    // 4) out = g_y @ W_o^T   (2048 x 1024 x 1024)
    {
        dim3 grid(1024 / 128, 2048 / 128);
        gemm_abt_kernel<1><<<grid, 256>>>(nullptr, qkvo_w + (size_t)3 * DD * DD, out, TT, DD, DD);
    }
}

// round 6
// speedup vs baseline: 1.3435x; 1.3435x over previous
#include <cuda_runtime.h>
#include <cuda_fp16.h>
#include <mma.h>
#include <math.h>

using namespace nvcuda;

#define TT 2048
#define DD 1024
#define NH 8
#define HD 128
#define GATE_IN 12

#define ATTN_SCALE 0.12f
#define RMS_EPS 1e-6f
#define LOG2E 1.4426950408889634f
#define SOFT_SHIFT 8.0f

static __device__ float g_qkv[(size_t)TT * 3 * DD];   // [t][3*D]
static __device__ float g_q[(size_t)NH * TT * HD];    // [h][t][hd]
static __device__ float g_k[(size_t)NH * TT * HD];
static __device__ float g_v[(size_t)NH * TT * HD];
static __device__ float g_y[(size_t)TT * DD];         // [t][h*HD+hd]

// truncate a float to tf32 precision (drop low 13 mantissa bits). No asm.
__device__ __forceinline__ float tf32_hi(float v) {
    return __uint_as_float(__float_as_uint(v) & 0xFFFFE000u);
}

// ---------------------------------------------------------------------------
// Split-tf32 GEMM via wmma: C[m][n] = sum_k A[m][k] * W[n][k]
// Block 128x128, BK=16, 256 threads = 8 warps in 2x4 grid; warp tile 64x32.
// Each input split a = hi + lo (tf32 each); D = ah*bh + al*bh + ah*bl.
// MODE 0: A = external (x), C = g_qkv.  MODE 1: A = g_y, C = external.
// ---------------------------------------------------------------------------
template <int MODE>
__global__ void __launch_bounds__(256) gemm_wmma_kernel(
    const float* __restrict__ Aext, const float* __restrict__ Bw,
    float* __restrict__ Cext, int M, int N, int K)
{
    const float* __restrict__ A = (MODE == 0) ? Aext : (const float*)g_y;
    float* __restrict__ C       = (MODE == 0) ? (float*)g_qkv : Cext;

    __shared__ float As[128][20];   // [m][k], pad row to 20 floats
    __shared__ float Bs[128][20];   // [n][k]

    const int tid = threadIdx.x;
    const int warp = tid >> 5;
    const int wm = warp >> 2;       // 0..1
    const int wn = warp & 3;        // 0..3
    const int bm = blockIdx.y * 128, bn = blockIdx.x * 128;
    const int lrow = tid >> 2;          // 0..63
    const int lc4 = (tid & 3) * 4;      // 0,4,8,12

    wmma::fragment<wmma::accumulator, 16, 16, 8, float> acc[4][2];
#pragma unroll
    for (int mt = 0; mt < 4; mt++)
#pragma unroll
        for (int nt = 0; nt < 2; nt++)
            wmma::fill_fragment(acc[mt][nt], 0.0f);

    for (int kt = 0; kt < K; kt += 16) {
        __syncthreads();
#pragma unroll
        for (int p = 0; p < 2; p++) {
            const int rr = lrow + p * 64;
            *(float4*)&As[rr][lc4] =
                *(const float4*)(A + (size_t)(bm + rr) * K + kt + lc4);
            *(float4*)&Bs[rr][lc4] =
                *(const float4*)(Bw + (size_t)(bn + rr) * K + kt + lc4);
        }
        __syncthreads();

#pragma unroll
        for (int ks = 0; ks < 16; ks += 8) {
            wmma::fragment<wmma::matrix_a, 16, 16, 8,
                           wmma::precision::tf32, wmma::row_major> ah[4], al[4];
#pragma unroll
            for (int mt = 0; mt < 4; mt++) {
                wmma::load_matrix_sync(ah[mt], &As[wm * 64 + mt * 16][ks], 20);
#pragma unroll
                for (int e = 0; e < ah[mt].num_elements; e++) {
                    float v = ah[mt].x[e];
                    float hi = tf32_hi(v);
                    ah[mt].x[e] = hi;
                    al[mt].x[e] = tf32_hi(v - hi);
                }
            }
            wmma::fragment<wmma::matrix_b, 16, 16, 8,
                           wmma::precision::tf32, wmma::col_major> bh[2], bl[2];
#pragma unroll
            for (int nt = 0; nt < 2; nt++) {
                wmma::load_matrix_sync(bh[nt], &Bs[wn * 32 + nt * 16][ks], 20);
#pragma unroll
                for (int e = 0; e < bh[nt].num_elements; e++) {
                    float v = bh[nt].x[e];
                    float hi = tf32_hi(v);
                    bh[nt].x[e] = hi;
                    bl[nt].x[e] = tf32_hi(v - hi);
                }
            }
#pragma unroll
            for (int mt = 0; mt < 4; mt++)
#pragma unroll
                for (int nt = 0; nt < 2; nt++) {
                    wmma::mma_sync(acc[mt][nt], ah[mt], bh[nt], acc[mt][nt]);
                    wmma::mma_sync(acc[mt][nt], al[mt], bh[nt], acc[mt][nt]);
                    wmma::mma_sync(acc[mt][nt], ah[mt], bl[nt], acc[mt][nt]);
                }
        }
    }

#pragma unroll
    for (int mt = 0; mt < 4; mt++)
#pragma unroll
        for (int nt = 0; nt < 2; nt++) {
            float* cp = C + (size_t)(bm + wm * 64 + mt * 16) * N
                          + bn + wn * 32 + nt * 16;
            wmma::store_matrix_sync(cp, acc[mt][nt], N, wmma::mem_row_major);
        }
}

// ---------------------------------------------------------------------------
// Postprocess: per (t,h): rms_norm + rotary on q,k; v = l0*v + l1*ve.
// ---------------------------------------------------------------------------
__global__ void postproc_kernel(const float* __restrict__ ve,
                                const float* __restrict__ lam,
                                const float* __restrict__ cosb,
                                const float* __restrict__ sinb)
{
    const int t = blockIdx.x >> 3;
    const int h = blockIdx.x & 7;
    const int hd = threadIdx.x;

    const float* rowp = g_qkv + (size_t)t * (3 * DD) + h * HD;
    float qv = rowp[hd];
    float kv = rowp[DD + hd];
    float vv = rowp[2 * DD + hd];

    float sq = qv * qv, sk = kv * kv;
#pragma unroll
    for (int o = 16; o; o >>= 1) {
        sq += __shfl_xor_sync(0xffffffffu, sq, o);
        sk += __shfl_xor_sync(0xffffffffu, sk, o);
    }
    __shared__ float red[2][4];
    int w = hd >> 5, lane = hd & 31;
    if (lane == 0) { red[0][w] = sq; red[1][w] = sk; }
    __syncthreads();
    sq = red[0][0] + red[0][1] + red[0][2] + red[0][3];
    sk = red[1][0] + red[1][1] + red[1][2] + red[1][3];
    float qr = rsqrtf(sq * (1.0f / HD) + RMS_EPS);
    float kr = rsqrtf(sk * (1.0f / HD) + RMS_EPS);

    __shared__ float qn[HD], kn[HD];
    qn[hd] = qv * qr;
    kn[hd] = kv * kr;
    __syncthreads();

    float qo, ko;
    if (hd < 64) {
        float cc = cosb[t * 64 + hd];
        float ss = sinb[t * 64 + hd];
        qo = qn[hd] * cc + qn[hd + 64] * ss;
        ko = kn[hd] * cc + kn[hd + 64] * ss;
    } else {
        int j = hd - 64;
        float cc = cosb[t * 64 + j];
        float ss = sinb[t * 64 + j];
        qo = -qn[j] * ss + qn[hd] * cc;
        ko = -kn[j] * ss + kn[hd] * cc;
    }
    const float lm0 = __ldg(lam);
    const float lm1 = __ldg(lam + 1);
    size_t oidx = ((size_t)h * TT + t) * HD + hd;
    g_q[oidx] = qo;
    g_k[oidx] = ko;
    g_v[oidx] = lm0 * vv + lm1 * ve[((size_t)t * NH + h) * HD + hd];
}

// ---------------------------------------------------------------------------
// Flash attention via wmma. Grid (32, 8), 128 threads = 4 warps.
// Block q-tile 64 rows; warp owns 16 rows. Key tiles of 32.
// QK: tf32 wmma with 3-term split (scale and log2e folded into Q).
// Softmax: fixed shift (no running max): p = exp2(s - 8); valid because
// scaled scores are bounded by 128*0.12*log2e < 23, so exp2 stays in range.
// O accumulators are never rescaled -> opaque fragment mapping is fine.
// PV: half wmma; normalize + gate in epilogue via smem staging.
// ---------------------------------------------------------------------------
__global__ void __launch_bounds__(128) flash_wmma_kernel(
    const float* __restrict__ x, const float* __restrict__ gate_w)
{
    // smem layout (bytes):
    //   0     : Ksm  32 x 132 f32  = 16896
    //   16896 : Vsm  32 x 136 half =  8704
    //   25600 : Ssm  per warp 16 x 36 f32 (2304 each, 4 warps) = 9216
    //   34816 : Psm  per warp 16 x 40 half (1280 each, 4 warps) = 5120
    //   total : 39936.  Epilogue reuses offset 0 as per-warp 16 x 132 f32.
    __shared__ __align__(16) unsigned char smraw[39936];
    float  (*Ksm)[132] = (float  (*)[132])(smraw);
    __half (*Vsm)[136] = (__half (*)[136])(smraw + 16896);

    const int h = blockIdx.y;
    const int qb = (int)gridDim.x - 1 - (int)blockIdx.x;   // heavy tiles first
    const int tid = threadIdx.x, warp = tid >> 5, lane = tid & 31;
    const int qbase = qb * 64;
    const int wrow0 = qbase + warp * 16;
    const int myrow = lane >> 1;
    const int myhalf = lane & 1;
    const int grow = wrow0 + myrow;

    float  (*Ssm_w)[36] = (float  (*)[36])(smraw + 25600 + warp * 2304);
    __half (*Psm_w)[40] = (__half (*)[40])(smraw + 34816 + warp * 1280);

    const float* Qh = g_q + (size_t)h * TT * HD;
    const float* Kh = g_k + (size_t)h * TT * HD;
    const float* Vh = g_v + (size_t)h * TT * HD;

    // Q fragments: raw f32, scaled by ATTN_SCALE * log2(e)
    const float QS = ATTN_SCALE * LOG2E;
    wmma::fragment<wmma::matrix_a, 16, 16, 8,
                   wmma::precision::tf32, wmma::row_major> qf[16];
#pragma unroll
    for (int kt = 0; kt < 16; kt++) {
        wmma::load_matrix_sync(qf[kt], Qh + (size_t)wrow0 * HD + kt * 8, HD);
#pragma unroll
        for (int e = 0; e < qf[kt].num_elements; e++) qf[kt].x[e] *= QS;
    }

    wmma::fragment<wmma::accumulator, 16, 16, 16, float> oacc[8];
#pragma unroll
    for (int nt = 0; nt < 8; nt++) wmma::fill_fragment(oacc[nt], 0.0f);
    float lrun = 0.0f;

    const int nkb = 2 * qb + 2;
    for (int kb = 0; kb < nkb; kb++) {
        const int kbase = kb * 32;
        __syncthreads();
        // cooperative load: K tile raw f32, V tile half
#pragma unroll
        for (int i = 0; i < 8; i++) {
            int idx = tid + i * 128;
            int rr = idx >> 5;
            int c4 = (idx & 31) * 4;
            float4 kv4 = *(const float4*)(Kh + (size_t)(kbase + rr) * HD + c4);
            *(float4*)&Ksm[rr][c4] = kv4;
            float4 vv4 = *(const float4*)(Vh + (size_t)(kbase + rr) * HD + c4);
            *(__half2*)&Vsm[rr][c4]     = __floats2half2_rn(vv4.x, vv4.y);
            *(__half2*)&Vsm[rr][c4 + 2] = __floats2half2_rn(vv4.z, vv4.w);
        }
        __syncthreads();

        const bool active = (kbase <= wrow0 + 15);   // warp-uniform
        if (active) {
            // S = Q K^T with 3-term tf32 split
            wmma::fragment<wmma::accumulator, 16, 16, 8, float> sacc[2];
            wmma::fill_fragment(sacc[0], 0.0f);
            wmma::fill_fragment(sacc[1], 0.0f);
#pragma unroll
            for (int kt = 0; kt < 16; kt++) {
                wmma::fragment<wmma::matrix_a, 16, 16, 8,
                               wmma::precision::tf32, wmma::row_major> ah, al;
#pragma unroll
                for (int e = 0; e < ah.num_elements; e++) {
                    float v = qf[kt].x[e];
                    float hi = tf32_hi(v);
                    ah.x[e] = hi;
                    al.x[e] = tf32_hi(v - hi);
                }
#pragma unroll
                for (int nt = 0; nt < 2; nt++) {
                    wmma::fragment<wmma::matrix_b, 16, 16, 8,
                                   wmma::precision::tf32, wmma::col_major> bh, bl;
                    wmma::load_matrix_sync(bh, &Ksm[nt * 16][kt * 8], 132);
#pragma unroll
                    for (int e = 0; e < bh.num_elements; e++) {
                        float v = bh.x[e];
                        float hi = tf32_hi(v);
                        bh.x[e] = hi;
                        bl.x[e] = tf32_hi(v - hi);
                    }
                    wmma::mma_sync(sacc[nt], ah, bh, sacc[nt]);
                    wmma::mma_sync(sacc[nt], al, bh, sacc[nt]);
                    wmma::mma_sync(sacc[nt], ah, bl, sacc[nt]);
                }
            }
            wmma::store_matrix_sync(&Ssm_w[0][0],  sacc[0], 36, wmma::mem_row_major);
            wmma::store_matrix_sync(&Ssm_w[0][16], sacc[1], 36, wmma::mem_row_major);
        }
        __syncwarp();
        if (active) {
            // softmax with fixed shift; causal mask; write P as half
            float lsum = 0.0f;
#pragma unroll
            for (int j = 0; j < 16; j++) {
                int col = myhalf * 16 + j;
                int gcol = kbase + col;
                float sv = Ssm_w[myrow][col];
                float p = (gcol <= grow) ? exp2f(sv - SOFT_SHIFT) : 0.0f;
                lsum += p;
                Psm_w[myrow][col] = __float2half(p);
            }
            lsum += __shfl_xor_sync(0xffffffffu, lsum, 1);
            lrun += lsum;
        }
        __syncwarp();
        if (active) {
            // O += P V  (half wmma)
#pragma unroll
            for (int ks = 0; ks < 2; ks++) {
                wmma::fragment<wmma::matrix_a, 16, 16, 16,
                               __half, wmma::row_major> pfrag;
                wmma::load_matrix_sync(pfrag, &Psm_w[0][ks * 16], 40);
#pragma unroll
                for (int nt = 0; nt < 8; nt++) {
                    wmma::fragment<wmma::matrix_b, 16, 16, 16,
                                   __half, wmma::row_major> vfrag;
                    wmma::load_matrix_sync(vfrag, &Vsm[ks * 16][nt * 16], 136);
                    wmma::mma_sync(oacc[nt], pfrag, vfrag, oacc[nt]);
                }
            }
        }
    }

    // epilogue: stage O to smem (reusing K and V space), normalize, gate, store
    __syncthreads();
    float (*Osm_w)[132] = (float (*)[132])(smraw + warp * 8448);
#pragma unroll
    for (int nt = 0; nt < 8; nt++)
        wmma::store_matrix_sync(&Osm_w[0][nt * 16], oacc[nt], 132,
                                wmma::mem_row_major);
    __syncwarp();

    float gd = 0.0f;
#pragma unroll
    for (int i = 0; i < GATE_IN; i++)
        gd += x[(size_t)grow * DD + i] * gate_w[h * GATE_IN + i];
    float gate = 1.0f / (1.0f + expf(-gd));
    float scale = gate / lrun;

    const int c0 = myhalf * 64;
    float* yrow = g_y + (size_t)grow * DD + h * HD;
#pragma unroll
    for (int j = 0; j < 16; j++) {
        float4 ov = *(float4*)&Osm_w[myrow][c0 + j * 4];
        ov.x *= scale; ov.y *= scale; ov.z *= scale; ov.w *= scale;
        *(float4*)(yrow + c0 + j * 4) = ov;
    }
}

// ---------------------------------------------------------------------------
extern "C" void kernel_launch(void* const* d_in, const int* in_sizes, int n_in,
                              void* d_out, int out_size)
{
    const float* x      = (const float*)d_in[0];  // (1,2048,1024)
    const float* qkvo_w = (const float*)d_in[1];  // (4,1024,1024)
    const float* gate_w = (const float*)d_in[2];  // (8,12)
    const float* ve     = (const float*)d_in[3];  // (1,2048,8,128)
    const float* lam    = (const float*)d_in[4];  // (2,)
    const float* cosb   = (const float*)d_in[5];  // (2048,64)
    const float* sinb   = (const float*)d_in[6];  // (2048,64)
    float* out = (float*)d_out;                   // (1,2048,1024)

    // 1) QKV projection -> g_qkv
    {
        dim3 grid(3072 / 128, 2048 / 128);
        gemm_wmma_kernel<0><<<grid, 256>>>(x, qkvo_w, nullptr, TT, 3 * DD, DD);
    }
    // 2) rms_norm + rotary + value mix
    postproc_kernel<<<TT * NH, 128>>>(ve, lam, cosb, sinb);
    // 3) causal flash attention + gate -> g_y
    {
        dim3 grid(TT / 64, NH);
        flash_wmma_kernel<<<grid, 128>>>(x, gate_w);
    }
    // 4) output projection
    {
        dim3 grid(1024 / 128, 2048 / 128);
        gemm_wmma_kernel<1><<<grid, 256>>>(nullptr, qkvo_w + (size_t)3 * DD * DD,
                                           out, TT, DD, DD);
    }
}